// round 1
// baseline (speedup 1.0000x reference)
#include <cuda_runtime.h>
#include <cstdint>
#include <cmath>

// ---------------- problem constants ----------------
#define T_TOK  8192          // B*S tokens
#define D_DIM  1024
#define E_EXP  8
#define H_DIM  4096
#define MPAD   17408         // T*K + E*128 padding headroom (multiple of 128)
#define MTILES 136           // MPAD / 128

// ---------------- scratch (device globals; no allocation allowed) ----------
__device__ float g_H1[(size_t)T_TOK * D_DIM];    // router hidden, 33.5 MB
__device__ float g_h [(size_t)MPAD * H_DIM];     // expert hidden, 285 MB
__device__ float g_y [(size_t)MPAD * D_DIM];     // expert out,    71 MB
__device__ int   g_topk_idx[T_TOK * 2];
__device__ float g_topk_w [T_TOK * 2];
__device__ int   g_counts [E_EXP];
__device__ int   g_offsets[E_EXP + 1];
__device__ int   g_fill   [E_EXP];
__device__ int   g_perm   [MPAD];
__device__ int   g_slot   [T_TOK * 2];
__device__ int   g_tile_expert[MTILES];

// ---------------- helpers ----------------
__device__ __forceinline__ float gelu_exact(float x) {
    return 0.5f * x * (1.0f + erff(x * 0.70710678118654752440f));
}
__device__ __forceinline__ uint32_t f2tf32(float x) {
    uint32_t r;
    asm("cvt.rna.tf32.f32 %0, %1;" : "=r"(r) : "f"(x));
    return r;
}
__device__ __forceinline__ void mma_tf32(float c[4],
                                         uint32_t a0, uint32_t a1, uint32_t a2, uint32_t a3,
                                         uint32_t b0, uint32_t b1) {
    asm volatile(
        "mma.sync.aligned.m16n8k8.row.col.f32.tf32.tf32.f32 "
        "{%0,%1,%2,%3}, {%4,%5,%6,%7}, {%8,%9}, {%0,%1,%2,%3};\n"
        : "+f"(c[0]), "+f"(c[1]), "+f"(c[2]), "+f"(c[3])
        : "r"(a0), "r"(a1), "r"(a2), "r"(a3), "r"(b0), "r"(b1));
}
__device__ __forceinline__ void cp_async16(void* smem_dst, const void* gmem_src, unsigned src_bytes) {
    unsigned d = (unsigned)__cvta_generic_to_shared(smem_dst);
    asm volatile("cp.async.ca.shared.global [%0], [%1], 16, %2;\n"
                 :: "r"(d), "l"(gmem_src), "r"(src_bytes) : "memory");
}

// ---------------- tiled TF32 GEMM ----------------
// C[M,N] = act( A[M,K] @ B[K,N] + bias[N] )
// BM=128 BN=128 BK=32, 256 threads, 8 warps (2x4), warp tile 64x32.
// SPLIT3: 3xTF32 split precision (near-fp32). GATHER: A rows via perm (pad rows -> 0).
// EXPERT: B/bias indexed by per-M-tile expert id (tiles with id<0 are skipped).
constexpr int BM = 128, BN = 128, BK = 32;
constexpr int AST = 36;                 // A smem stride (conflict-free)
constexpr int BST = 136;                // B smem stride (conflict-free)
constexpr int A_ELE = BM * AST;         // 4608
constexpr int B_ELE = BK * BST;         // 4352
constexpr int GEMM_SMEM_BYTES = (2 * A_ELE + 2 * B_ELE) * 4;  // 71680

template<bool SPLIT3, bool DO_GELU, bool GATHER, bool EXPERT>
__global__ __launch_bounds__(256)
void gemm_tf32_kernel(const float* __restrict__ A,
                      const float* __restrict__ Bbase,
                      const float* __restrict__ biasBase,
                      float* __restrict__ C,
                      int N, int Kdim,
                      const int* __restrict__ perm,
                      const int* __restrict__ tile_expert,
                      long strideB, int strideBias)
{
    extern __shared__ float smem[];
    float* As = smem;                       // [2][A_ELE]
    float* Bs = smem + 2 * A_ELE;           // [2][B_ELE]

    const int mtile = blockIdx.y;
    const int ntile = blockIdx.x;

    const float* Bp   = Bbase;
    const float* bias = biasBase;
    if (EXPERT) {
        int e = tile_expert[mtile];
        if (e < 0) return;                  // whole block exits uniformly
        Bp   += (long)e * strideB;
        bias += (long)e * strideBias;
    }

    const int tid   = threadIdx.x;
    const int lane  = tid & 31;
    const int warp  = tid >> 5;
    const int warpM = warp & 1;             // 0..1
    const int warpN = warp >> 1;            // 0..3
    const int mbase = mtile * BM;
    const int nbase = ntile * BN;

    float acc[4][4][4];
    #pragma unroll
    for (int mi = 0; mi < 4; mi++)
        #pragma unroll
        for (int ni = 0; ni < 4; ni++)
            #pragma unroll
            for (int r = 0; r < 4; r++) acc[mi][ni][r] = 0.0f;

    const int KT = Kdim / BK;

    auto load_tiles = [&](int kt, int stage) {
        const int k0 = kt * BK;
        // A tile: 128 rows x 32 cols fp32; 8 16B-chunks per row; 4 chunks/thread
        #pragma unroll
        for (int i = 0; i < 4; i++) {
            int c   = tid + i * 256;
            int r   = c >> 3;
            int col = (c & 7) * 4;
            const float* src;
            unsigned sz = 16;
            if (GATHER) {
                int g = perm[mbase + r];
                if (g < 0) { sz = 0; src = A; }
                else        src = A + (long)g * Kdim + k0 + col;
            } else {
                src = A + (long)(mbase + r) * Kdim + k0 + col;
            }
            cp_async16(&As[stage * A_ELE + r * AST + col], src, sz);
        }
        // B tile: 32 rows x 128 cols fp32; 32 chunks/row; 4 chunks/thread
        #pragma unroll
        for (int i = 0; i < 4; i++) {
            int c   = tid + i * 256;
            int r   = c >> 5;
            int col = (c & 31) * 4;
            const float* src = Bp + (long)(k0 + r) * N + nbase + col;
            cp_async16(&Bs[stage * B_ELE + r * BST + col], src, 16);
        }
        asm volatile("cp.async.commit_group;\n" ::: "memory");
    };

    load_tiles(0, 0);
    for (int kt = 0; kt < KT; kt++) {
        if (kt + 1 < KT) {
            load_tiles(kt + 1, (kt + 1) & 1);
            asm volatile("cp.async.wait_group 1;\n" ::: "memory");
        } else {
            asm volatile("cp.async.wait_group 0;\n" ::: "memory");
        }
        __syncthreads();

        const float* as = As + (kt & 1) * A_ELE;
        const float* bs = Bs + (kt & 1) * B_ELE;

        #pragma unroll
        for (int kk = 0; kk < 4; kk++) {
            const int k = kk * 8 + (lane & 3);

            uint32_t ah[4][4], al[4][4];
            #pragma unroll
            for (int mi = 0; mi < 4; mi++) {
                int m0 = warpM * 64 + mi * 16 + (lane >> 2);
                float v0 = as[(m0    ) * AST + k    ];
                float v1 = as[(m0 + 8) * AST + k    ];
                float v2 = as[(m0    ) * AST + k + 4];
                float v3 = as[(m0 + 8) * AST + k + 4];
                ah[mi][0] = f2tf32(v0); ah[mi][1] = f2tf32(v1);
                ah[mi][2] = f2tf32(v2); ah[mi][3] = f2tf32(v3);
                if (SPLIT3) {
                    al[mi][0] = f2tf32(v0 - __uint_as_float(ah[mi][0]));
                    al[mi][1] = f2tf32(v1 - __uint_as_float(ah[mi][1]));
                    al[mi][2] = f2tf32(v2 - __uint_as_float(ah[mi][2]));
                    al[mi][3] = f2tf32(v3 - __uint_as_float(ah[mi][3]));
                }
            }
            uint32_t bh[4][2], bl[4][2];
            #pragma unroll
            for (int ni = 0; ni < 4; ni++) {
                int n0 = warpN * 32 + ni * 8 + (lane >> 2);
                float w0 = bs[(k    ) * BST + n0];
                float w1 = bs[(k + 4) * BST + n0];
                bh[ni][0] = f2tf32(w0); bh[ni][1] = f2tf32(w1);
                if (SPLIT3) {
                    bl[ni][0] = f2tf32(w0 - __uint_as_float(bh[ni][0]));
                    bl[ni][1] = f2tf32(w1 - __uint_as_float(bh[ni][1]));
                }
            }
            #pragma unroll
            for (int mi = 0; mi < 4; mi++)
                #pragma unroll
                for (int ni = 0; ni < 4; ni++) {
                    if (SPLIT3) {
                        // lo terms first, hi*hi last (accumulate small-to-large)
                        mma_tf32(acc[mi][ni], ah[mi][0], ah[mi][1], ah[mi][2], ah[mi][3],
                                 bl[ni][0], bl[ni][1]);
                        mma_tf32(acc[mi][ni], al[mi][0], al[mi][1], al[mi][2], al[mi][3],
                                 bh[ni][0], bh[ni][1]);
                    }
                    mma_tf32(acc[mi][ni], ah[mi][0], ah[mi][1], ah[mi][2], ah[mi][3],
                             bh[ni][0], bh[ni][1]);
                }
        }
        __syncthreads();
    }

    // epilogue: bias (+ GELU) and store
    #pragma unroll
    for (int mi = 0; mi < 4; mi++) {
        #pragma unroll
        for (int ni = 0; ni < 4; ni++) {
            int row0 = mbase + warpM * 64 + mi * 16 + (lane >> 2);
            int col0 = nbase + warpN * 32 + ni * 8 + (lane & 3) * 2;
            float bv0 = bias[col0], bv1 = bias[col0 + 1];
            float v00 = acc[mi][ni][0] + bv0;
            float v01 = acc[mi][ni][1] + bv1;
            float v10 = acc[mi][ni][2] + bv0;
            float v11 = acc[mi][ni][3] + bv1;
            if (DO_GELU) {
                v00 = gelu_exact(v00); v01 = gelu_exact(v01);
                v10 = gelu_exact(v10); v11 = gelu_exact(v11);
            }
            *reinterpret_cast<float2*>(&C[(long)(row0    ) * N + col0]) = make_float2(v00, v01);
            *reinterpret_cast<float2*>(&C[(long)(row0 + 8) * N + col0]) = make_float2(v10, v11);
        }
    }
}

// ---------------- routing kernels ----------------
__global__ void init_kernel(int* __restrict__ perm, int* __restrict__ counts)
{
    int i = blockIdx.x * 256 + threadIdx.x;
    if (i < MPAD)  perm[i] = -1;
    if (i < E_EXP) counts[i] = 0;
}

// one warp per token: logits = H1[t,:] @ Wr2 + br2; softmax; top-2; renorm weights
__global__ void route_kernel(const float* __restrict__ H1,
                             const float* __restrict__ Wr2,
                             const float* __restrict__ br2,
                             int*   __restrict__ topk_idx,
                             float* __restrict__ topk_w,
                             int*   __restrict__ counts)
{
    int warp = threadIdx.x >> 5, lane = threadIdx.x & 31;
    int t = blockIdx.x * 8 + warp;
    const float* h = H1 + (long)t * D_DIM;

    float acc[E_EXP];
    #pragma unroll
    for (int e = 0; e < E_EXP; e++) acc[e] = 0.0f;

    #pragma unroll 4
    for (int i = 0; i < D_DIM / 32; i++) {
        int d = i * 32 + lane;
        float hv = h[d];
        const float4* w4 = reinterpret_cast<const float4*>(Wr2 + (long)d * E_EXP);
        float4 wa = w4[0], wb = w4[1];
        acc[0] += hv * wa.x; acc[1] += hv * wa.y; acc[2] += hv * wa.z; acc[3] += hv * wa.w;
        acc[4] += hv * wb.x; acc[5] += hv * wb.y; acc[6] += hv * wb.z; acc[7] += hv * wb.w;
    }
    #pragma unroll
    for (int e = 0; e < E_EXP; e++)
        #pragma unroll
        for (int off = 16; off; off >>= 1)
            acc[e] += __shfl_xor_sync(0xFFFFFFFFu, acc[e], off);

    if (lane == 0) {
        float l[E_EXP];
        #pragma unroll
        for (int e = 0; e < E_EXP; e++) l[e] = acc[e] + br2[e];
        // top-2 on logits (monotonic w.r.t. softmax probs); ties -> lowest index (JAX top_k)
        int e0 = 0;
        #pragma unroll
        for (int e = 1; e < E_EXP; e++) if (l[e] > l[e0]) e0 = e;
        int e1 = -1;
        #pragma unroll
        for (int e = 0; e < E_EXP; e++)
            if (e != e0 && (e1 < 0 || l[e] > l[e1])) e1 = e;
        float m  = l[e0];                       // l[e0] >= l[e1]
        float p0 = expf(l[e0] - m);
        float p1 = expf(l[e1] - m);
        float inv = 1.0f / (p0 + p1);
        topk_idx[t * 2]     = e0;
        topk_idx[t * 2 + 1] = e1;
        topk_w[t * 2]       = p0 * inv;
        topk_w[t * 2 + 1]   = p1 * inv;
        atomicAdd(&counts[e0], 1);
        atomicAdd(&counts[e1], 1);
    }
}

__global__ void scan_kernel(const int* __restrict__ counts,
                            int* __restrict__ offsets,
                            int* __restrict__ fill,
                            int* __restrict__ tile_expert)
{
    if (threadIdx.x != 0) return;
    int off = 0;
    for (int e = 0; e < E_EXP; e++) {
        offsets[e] = off;
        off += (counts[e] + 127) & ~127;   // pad each segment to 128
        fill[e] = 0;
    }
    offsets[E_EXP] = off;
    int e = 0;
    for (int tile = 0; tile < MTILES; tile++) {
        int r = tile * 128;
        if (r >= off) { tile_expert[tile] = -1; continue; }
        while (e < E_EXP && r >= offsets[e + 1]) e++;
        tile_expert[tile] = e;
    }
}

__global__ void fill_kernel(const int* __restrict__ topk_idx,
                            const int* __restrict__ offsets,
                            int* __restrict__ fill,
                            int* __restrict__ perm,
                            int* __restrict__ slot)
{
    int t = blockIdx.x * 256 + threadIdx.x;
    if (t >= T_TOK) return;
    #pragma unroll
    for (int k = 0; k < 2; k++) {
        int e   = topk_idx[t * 2 + k];
        int pos = offsets[e] + atomicAdd(&fill[e], 1);
        perm[pos]       = t;
        slot[t * 2 + k] = pos;
    }
}

__global__ void combine_kernel(const float* __restrict__ y,
                               const int*   __restrict__ slot,
                               const float* __restrict__ w,
                               float* __restrict__ out)
{
    long i = (long)blockIdx.x * 256 + threadIdx.x;     // over T*D/4
    int  t = (int)(i >> 8);                            // D/4 = 256 vec4 per token
    int  c = ((int)i & 255) * 4;
    int   s0 = slot[t * 2], s1 = slot[t * 2 + 1];
    float w0 = w[t * 2],    w1 = w[t * 2 + 1];
    float4 y0 = *reinterpret_cast<const float4*>(y + (long)s0 * D_DIM + c);
    float4 y1 = *reinterpret_cast<const float4*>(y + (long)s1 * D_DIM + c);
    float4 o;
    o.x = w0 * y0.x + w1 * y1.x;
    o.y = w0 * y0.y + w1 * y1.y;
    o.z = w0 * y0.z + w1 * y1.z;
    o.w = w0 * y0.w + w1 * y1.w;
    *reinterpret_cast<float4*>(out + (long)t * D_DIM + c) = o;
}

// ---------------- launch ----------------
extern "C" void kernel_launch(void* const* d_in, const int* in_sizes, int n_in,
                              void* d_out, int out_size)
{
    const float* x   = (const float*)d_in[0];
    const float* Wr1 = (const float*)d_in[1];
    const float* br1 = (const float*)d_in[2];
    const float* Wr2 = (const float*)d_in[3];
    const float* br2 = (const float*)d_in[4];
    const float* W1  = (const float*)d_in[5];
    const float* b1  = (const float*)d_in[6];
    const float* W2  = (const float*)d_in[7];
    const float* b2  = (const float*)d_in[8];
    float* out = (float*)d_out;

    void *pH1, *ph, *py, *pti, *ptw, *pc, *po, *pf, *pp, *ps, *pte;
    cudaGetSymbolAddress(&pH1, g_H1);
    cudaGetSymbolAddress(&ph,  g_h);
    cudaGetSymbolAddress(&py,  g_y);
    cudaGetSymbolAddress(&pti, g_topk_idx);
    cudaGetSymbolAddress(&ptw, g_topk_w);
    cudaGetSymbolAddress(&pc,  g_counts);
    cudaGetSymbolAddress(&po,  g_offsets);
    cudaGetSymbolAddress(&pf,  g_fill);
    cudaGetSymbolAddress(&pp,  g_perm);
    cudaGetSymbolAddress(&ps,  g_slot);
    cudaGetSymbolAddress(&pte, g_tile_expert);

    cudaFuncSetAttribute(gemm_tf32_kernel<true,  true,  false, false>,
                         cudaFuncAttributeMaxDynamicSharedMemorySize, GEMM_SMEM_BYTES);
    cudaFuncSetAttribute(gemm_tf32_kernel<false, true,  true,  true>,
                         cudaFuncAttributeMaxDynamicSharedMemorySize, GEMM_SMEM_BYTES);
    cudaFuncSetAttribute(gemm_tf32_kernel<false, false, false, true>,
                         cudaFuncAttributeMaxDynamicSharedMemorySize, GEMM_SMEM_BYTES);

    // 1) init scratch
    init_kernel<<<(MPAD + 255) / 256, 256>>>((int*)pp, (int*)pc);

    // 2) router hidden: H1 = GELU(x @ Wr1 + br1), 3xTF32 split (near-fp32 for stable top-k)
    gemm_tf32_kernel<true, true, false, false>
        <<<dim3(D_DIM / BN, T_TOK / BM), 256, GEMM_SMEM_BYTES>>>(
            x, Wr1, br1, (float*)pH1, D_DIM, D_DIM, nullptr, nullptr, 0, 0);

    // 3) logits + softmax + top-2 + counts
    route_kernel<<<T_TOK / 8, 256>>>((const float*)pH1, Wr2, br2,
                                     (int*)pti, (float*)ptw, (int*)pc);

    // 4) padded segment offsets + tile->expert map
    scan_kernel<<<1, 32>>>((const int*)pc, (int*)po, (int*)pf, (int*)pte);

    // 5) build permutation + token slots
    fill_kernel<<<T_TOK / 256, 256>>>((const int*)pti, (const int*)po,
                                      (int*)pf, (int*)pp, (int*)ps);

    // 6) expert layer 1 (grouped, gathered): h = GELU(x[perm] @ W1[e] + b1[e])
    gemm_tf32_kernel<false, true, true, true>
        <<<dim3(H_DIM / BN, MTILES), 256, GEMM_SMEM_BYTES>>>(
            x, W1, b1, (float*)ph, H_DIM, D_DIM,
            (const int*)pp, (const int*)pte, (long)D_DIM * H_DIM, H_DIM);

    // 7) expert layer 2 (grouped): y = h @ W2[e] + b2[e]
    gemm_tf32_kernel<false, false, false, true>
        <<<dim3(D_DIM / BN, MTILES), 256, GEMM_SMEM_BYTES>>>(
            (const float*)ph, W2, b2, (float*)py, D_DIM, H_DIM,
            nullptr, (const int*)pte, (long)H_DIM * D_DIM, D_DIM);

    // 8) weighted combine via recorded slots (deterministic; no atomics on out)
    combine_kernel<<<(T_TOK * D_DIM / 4) / 256, 256>>>(
        (const float*)py, (const int*)ps, (const float*)ptw, out);
}

// round 2
// speedup vs baseline: 1.0035x; 1.0035x over previous
#include <cuda_runtime.h>
#include <cstdint>
#include <cmath>

// ---------------- problem constants ----------------
#define T_TOK  8192          // B*S tokens
#define D_DIM  1024
#define E_EXP  8
#define H_DIM  4096
#define MPAD   17408         // T*K + E*128 padding headroom (multiple of 128)
#define MTILES 136           // MPAD / 128

#define W1E  33554432L       // 8*1024*4096
#define W2E  33554432L
#define XE   8388608L        // 8192*1024
#define WR1E 1048576L        // 1024*1024

// ---------------- scratch (device globals; no allocation allowed) ----------
__device__ float g_H1[(size_t)T_TOK * D_DIM];    // router hidden
__device__ float g_h [(size_t)MPAD * H_DIM];     // expert hidden (pre-rounded tf32)
__device__ float g_y [(size_t)MPAD * D_DIM];     // expert out
__device__ float g_W1c[W1E];                     // rna-rounded W1
__device__ float g_W2c[W2E];                     // rna-rounded W2
__device__ float g_xhi[XE];                      // rna(x)
__device__ float g_xlo[XE];                      // rna(x - xhi)
__device__ float g_wr1hi[WR1E];
__device__ float g_wr1lo[WR1E];
__device__ int   g_topk_idx[T_TOK * 2];
__device__ float g_topk_w [T_TOK * 2];
__device__ int   g_counts [E_EXP];
__device__ int   g_perm   [MPAD];
__device__ int   g_slot   [T_TOK * 2];
__device__ int   g_tile_expert[MTILES];
__device__ int   g_done;

// ---------------- helpers ----------------
__device__ __forceinline__ float gelu_exact(float x) {
    return 0.5f * x * (1.0f + erff(x * 0.70710678118654752440f));
}
__device__ __forceinline__ uint32_t f2tf32(float x) {
    uint32_t r;
    asm("cvt.rna.tf32.f32 %0, %1;" : "=r"(r) : "f"(x));
    return r;
}
__device__ __forceinline__ float rna(float x) { return __uint_as_float(f2tf32(x)); }

__device__ __forceinline__ void mma_tf32(float c[4],
                                         uint32_t a0, uint32_t a1, uint32_t a2, uint32_t a3,
                                         uint32_t b0, uint32_t b1) {
    asm volatile(
        "mma.sync.aligned.m16n8k8.row.col.f32.tf32.tf32.f32 "
        "{%0,%1,%2,%3}, {%4,%5,%6,%7}, {%8,%9}, {%0,%1,%2,%3};\n"
        : "+f"(c[0]), "+f"(c[1]), "+f"(c[2]), "+f"(c[3])
        : "r"(a0), "r"(a1), "r"(a2), "r"(a3), "r"(b0), "r"(b1));
}
__device__ __forceinline__ void cp_async16(void* smem_dst, const void* gmem_src, unsigned src_bytes) {
    unsigned d = (unsigned)__cvta_generic_to_shared(smem_dst);
    asm volatile("cp.async.ca.shared.global [%0], [%1], 16, %2;\n"
                 :: "r"(d), "l"(gmem_src), "r"(src_bytes) : "memory");
}

// ---------------- GEMM tiling constants ----------------
constexpr int BM = 128, BN = 128, BK = 32;
constexpr int AST = 36;                 // A smem stride (conflict-free)
constexpr int BST = 136;                // B smem stride (conflict-free)
constexpr int A_ELE = BM * AST;         // 4608
constexpr int B_ELE = BK * BST;         // 4352
constexpr int GEMM_SMEM_BYTES  = (2 * A_ELE + 2 * B_ELE) * 4;       // 71680
constexpr int SPLIT_SMEM_BYTES = 2 * GEMM_SMEM_BYTES;               // 143360

// ---------------- prep: init + round weights + split x/Wr1 ----------------
__global__ void prep_kernel(const float4* __restrict__ W1, const float4* __restrict__ W2,
                            const float4* __restrict__ x,  const float4* __restrict__ Wr1,
                            float4* __restrict__ W1c, float4* __restrict__ W2c,
                            float4* __restrict__ xhi, float4* __restrict__ xlo,
                            float4* __restrict__ wr1hi, float4* __restrict__ wr1lo,
                            int* __restrict__ perm, int* __restrict__ counts,
                            int* __restrict__ done)
{
    long i = (long)blockIdx.x * 256 + threadIdx.x;
    if (i < MPAD)  perm[i] = -1;
    if (i < E_EXP) counts[i] = 0;
    if (i == 0)    *done = 0;

    if (i < W1E / 4) {
        float4 v = W1[i];
        W1c[i] = make_float4(rna(v.x), rna(v.y), rna(v.z), rna(v.w));
    } else if (i < (W1E + W2E) / 4) {
        long j = i - W1E / 4;
        float4 v = W2[j];
        W2c[j] = make_float4(rna(v.x), rna(v.y), rna(v.z), rna(v.w));
    } else if (i < (W1E + W2E + XE) / 4) {
        long j = i - (W1E + W2E) / 4;
        float4 v = x[j];
        float4 h = make_float4(rna(v.x), rna(v.y), rna(v.z), rna(v.w));
        xhi[j] = h;
        xlo[j] = make_float4(rna(v.x - h.x), rna(v.y - h.y), rna(v.z - h.z), rna(v.w - h.w));
    } else if (i < (W1E + W2E + XE + WR1E) / 4) {
        long j = i - (W1E + W2E + XE) / 4;
        float4 v = Wr1[j];
        float4 h = make_float4(rna(v.x), rna(v.y), rna(v.z), rna(v.w));
        wr1hi[j] = h;
        wr1lo[j] = make_float4(rna(v.x - h.x), rna(v.y - h.y), rna(v.z - h.z), rna(v.w - h.w));
    }
}

// ---------------- single-pass TF32 GEMM (pre-rounded operands) ----------------
// C[M,N] = act( A[M,K] @ B[K,N] + bias[N] ); ROUND_OUT rounds stores to tf32.
template<bool DO_GELU, bool ROUND_OUT, bool GATHER, bool EXPERT>
__global__ __launch_bounds__(256, 2)
void gemm_tf32_kernel(const float* __restrict__ A,
                      const float* __restrict__ Bbase,
                      const float* __restrict__ biasBase,
                      float* __restrict__ C,
                      int N, int Kdim,
                      const int* __restrict__ perm,
                      const int* __restrict__ tile_expert,
                      long strideB, int strideBias)
{
    extern __shared__ float smem[];
    float* As = smem;                       // [2][A_ELE]
    float* Bs = smem + 2 * A_ELE;           // [2][B_ELE]

    const int mtile = blockIdx.y;
    const int ntile = blockIdx.x;

    const float* Bp   = Bbase;
    const float* bias = biasBase;
    if (EXPERT) {
        int e = tile_expert[mtile];
        if (e < 0) return;                  // whole block exits uniformly
        Bp   += (long)e * strideB;
        bias += (long)e * strideBias;
    }

    const int tid   = threadIdx.x;
    const int lane  = tid & 31;
    const int warp  = tid >> 5;
    const int warpM = warp & 1;
    const int warpN = warp >> 1;
    const int mbase = mtile * BM;
    const int nbase = ntile * BN;

    float acc[4][4][4];
    #pragma unroll
    for (int mi = 0; mi < 4; mi++)
        #pragma unroll
        for (int ni = 0; ni < 4; ni++)
            #pragma unroll
            for (int r = 0; r < 4; r++) acc[mi][ni][r] = 0.0f;

    const int KT = Kdim / BK;

    auto load_tiles = [&](int kt, int stage) {
        const int k0 = kt * BK;
        #pragma unroll
        for (int i = 0; i < 4; i++) {
            int c   = tid + i * 256;
            int r   = c >> 3;
            int col = (c & 7) * 4;
            const float* src;
            unsigned sz = 16;
            if (GATHER) {
                int g = perm[mbase + r];
                if (g < 0) { sz = 0; src = A; }
                else        src = A + (long)g * Kdim + k0 + col;
            } else {
                src = A + (long)(mbase + r) * Kdim + k0 + col;
            }
            cp_async16(&As[stage * A_ELE + r * AST + col], src, sz);
        }
        #pragma unroll
        for (int i = 0; i < 4; i++) {
            int c   = tid + i * 256;
            int r   = c >> 5;
            int col = (c & 31) * 4;
            const float* src = Bp + (long)(k0 + r) * N + nbase + col;
            cp_async16(&Bs[stage * B_ELE + r * BST + col], src, 16);
        }
        asm volatile("cp.async.commit_group;\n" ::: "memory");
    };

    load_tiles(0, 0);
    for (int kt = 0; kt < KT; kt++) {
        if (kt + 1 < KT) {
            load_tiles(kt + 1, (kt + 1) & 1);
            asm volatile("cp.async.wait_group 1;\n" ::: "memory");
        } else {
            asm volatile("cp.async.wait_group 0;\n" ::: "memory");
        }
        __syncthreads();

        const float* as = As + (kt & 1) * A_ELE;
        const float* bs = Bs + (kt & 1) * B_ELE;

        #pragma unroll
        for (int kk = 0; kk < 4; kk++) {
            const int k = kk * 8 + (lane & 3);

            uint32_t ah[4][4];
            #pragma unroll
            for (int mi = 0; mi < 4; mi++) {
                int m0 = warpM * 64 + mi * 16 + (lane >> 2);
                ah[mi][0] = __float_as_uint(as[(m0    ) * AST + k    ]);
                ah[mi][1] = __float_as_uint(as[(m0 + 8) * AST + k    ]);
                ah[mi][2] = __float_as_uint(as[(m0    ) * AST + k + 4]);
                ah[mi][3] = __float_as_uint(as[(m0 + 8) * AST + k + 4]);
            }
            uint32_t bh[4][2];
            #pragma unroll
            for (int ni = 0; ni < 4; ni++) {
                int n0 = warpN * 32 + ni * 8 + (lane >> 2);
                bh[ni][0] = __float_as_uint(bs[(k    ) * BST + n0]);
                bh[ni][1] = __float_as_uint(bs[(k + 4) * BST + n0]);
            }
            #pragma unroll
            for (int mi = 0; mi < 4; mi++)
                #pragma unroll
                for (int ni = 0; ni < 4; ni++)
                    mma_tf32(acc[mi][ni], ah[mi][0], ah[mi][1], ah[mi][2], ah[mi][3],
                             bh[ni][0], bh[ni][1]);
        }
        __syncthreads();
    }

    #pragma unroll
    for (int mi = 0; mi < 4; mi++) {
        #pragma unroll
        for (int ni = 0; ni < 4; ni++) {
            int row0 = mbase + warpM * 64 + mi * 16 + (lane >> 2);
            int col0 = nbase + warpN * 32 + ni * 8 + (lane & 3) * 2;
            float bv0 = bias[col0], bv1 = bias[col0 + 1];
            float v00 = acc[mi][ni][0] + bv0;
            float v01 = acc[mi][ni][1] + bv1;
            float v10 = acc[mi][ni][2] + bv0;
            float v11 = acc[mi][ni][3] + bv1;
            if (DO_GELU) {
                v00 = gelu_exact(v00); v01 = gelu_exact(v01);
                v10 = gelu_exact(v10); v11 = gelu_exact(v11);
            }
            if (ROUND_OUT) {
                v00 = rna(v00); v01 = rna(v01); v10 = rna(v10); v11 = rna(v11);
            }
            *reinterpret_cast<float2*>(&C[(long)(row0    ) * N + col0]) = make_float2(v00, v01);
            *reinterpret_cast<float2*>(&C[(long)(row0 + 8) * N + col0]) = make_float2(v10, v11);
        }
    }
}

// ---------------- 3xTF32 split GEMM (pre-split hi/lo operands) -------------
// C = GELU( A @ B + bias ) at near-fp32 accuracy. Used for the router hidden.
__global__ __launch_bounds__(256)
void gemm_split3_kernel(const float* __restrict__ Ahi, const float* __restrict__ Alo,
                        const float* __restrict__ Bhi_, const float* __restrict__ Blo_,
                        const float* __restrict__ bias,
                        float* __restrict__ C, int N, int Kdim)
{
    extern __shared__ float smem[];
    float* AsH = smem;                       // [2][A_ELE]
    float* AsL = AsH + 2 * A_ELE;
    float* BsH = AsL + 2 * A_ELE;            // [2][B_ELE]
    float* BsL = BsH + 2 * B_ELE;

    const int mtile = blockIdx.y;
    const int ntile = blockIdx.x;
    const int tid   = threadIdx.x;
    const int lane  = tid & 31;
    const int warp  = tid >> 5;
    const int warpM = warp & 1;
    const int warpN = warp >> 1;
    const int mbase = mtile * BM;
    const int nbase = ntile * BN;

    float acc[4][4][4];
    #pragma unroll
    for (int mi = 0; mi < 4; mi++)
        #pragma unroll
        for (int ni = 0; ni < 4; ni++)
            #pragma unroll
            for (int r = 0; r < 4; r++) acc[mi][ni][r] = 0.0f;

    const int KT = Kdim / BK;

    auto load_tiles = [&](int kt, int stage) {
        const int k0 = kt * BK;
        #pragma unroll
        for (int i = 0; i < 4; i++) {
            int c   = tid + i * 256;
            int r   = c >> 3;
            int col = (c & 7) * 4;
            long off = (long)(mbase + r) * Kdim + k0 + col;
            cp_async16(&AsH[stage * A_ELE + r * AST + col], Ahi + off, 16);
            cp_async16(&AsL[stage * A_ELE + r * AST + col], Alo + off, 16);
        }
        #pragma unroll
        for (int i = 0; i < 4; i++) {
            int c   = tid + i * 256;
            int r   = c >> 5;
            int col = (c & 31) * 4;
            long off = (long)(k0 + r) * N + nbase + col;
            cp_async16(&BsH[stage * B_ELE + r * BST + col], Bhi_ + off, 16);
            cp_async16(&BsL[stage * B_ELE + r * BST + col], Blo_ + off, 16);
        }
        asm volatile("cp.async.commit_group;\n" ::: "memory");
    };

    load_tiles(0, 0);
    for (int kt = 0; kt < KT; kt++) {
        if (kt + 1 < KT) {
            load_tiles(kt + 1, (kt + 1) & 1);
            asm volatile("cp.async.wait_group 1;\n" ::: "memory");
        } else {
            asm volatile("cp.async.wait_group 0;\n" ::: "memory");
        }
        __syncthreads();

        const float* ash = AsH + (kt & 1) * A_ELE;
        const float* asl = AsL + (kt & 1) * A_ELE;
        const float* bsh = BsH + (kt & 1) * B_ELE;
        const float* bsl = BsL + (kt & 1) * B_ELE;

        #pragma unroll
        for (int kk = 0; kk < 4; kk++) {
            const int k = kk * 8 + (lane & 3);

            uint32_t ah[4][4], al[4][4];
            #pragma unroll
            for (int mi = 0; mi < 4; mi++) {
                int m0 = warpM * 64 + mi * 16 + (lane >> 2);
                ah[mi][0] = __float_as_uint(ash[(m0    ) * AST + k    ]);
                ah[mi][1] = __float_as_uint(ash[(m0 + 8) * AST + k    ]);
                ah[mi][2] = __float_as_uint(ash[(m0    ) * AST + k + 4]);
                ah[mi][3] = __float_as_uint(ash[(m0 + 8) * AST + k + 4]);
                al[mi][0] = __float_as_uint(asl[(m0    ) * AST + k    ]);
                al[mi][1] = __float_as_uint(asl[(m0 + 8) * AST + k    ]);
                al[mi][2] = __float_as_uint(asl[(m0    ) * AST + k + 4]);
                al[mi][3] = __float_as_uint(asl[(m0 + 8) * AST + k + 4]);
            }
            uint32_t bh[4][2], bl[4][2];
            #pragma unroll
            for (int ni = 0; ni < 4; ni++) {
                int n0 = warpN * 32 + ni * 8 + (lane >> 2);
                bh[ni][0] = __float_as_uint(bsh[(k    ) * BST + n0]);
                bh[ni][1] = __float_as_uint(bsh[(k + 4) * BST + n0]);
                bl[ni][0] = __float_as_uint(bsl[(k    ) * BST + n0]);
                bl[ni][1] = __float_as_uint(bsl[(k + 4) * BST + n0]);
            }
            #pragma unroll
            for (int mi = 0; mi < 4; mi++)
                #pragma unroll
                for (int ni = 0; ni < 4; ni++) {
                    mma_tf32(acc[mi][ni], ah[mi][0], ah[mi][1], ah[mi][2], ah[mi][3],
                             bl[ni][0], bl[ni][1]);
                    mma_tf32(acc[mi][ni], al[mi][0], al[mi][1], al[mi][2], al[mi][3],
                             bh[ni][0], bh[ni][1]);
                    mma_tf32(acc[mi][ni], ah[mi][0], ah[mi][1], ah[mi][2], ah[mi][3],
                             bh[ni][0], bh[ni][1]);
                }
        }
        __syncthreads();
    }

    #pragma unroll
    for (int mi = 0; mi < 4; mi++) {
        #pragma unroll
        for (int ni = 0; ni < 4; ni++) {
            int row0 = mbase + warpM * 64 + mi * 16 + (lane >> 2);
            int col0 = nbase + warpN * 32 + ni * 8 + (lane & 3) * 2;
            float bv0 = bias[col0], bv1 = bias[col0 + 1];
            float v00 = gelu_exact(acc[mi][ni][0] + bv0);
            float v01 = gelu_exact(acc[mi][ni][1] + bv1);
            float v10 = gelu_exact(acc[mi][ni][2] + bv0);
            float v11 = gelu_exact(acc[mi][ni][3] + bv1);
            *reinterpret_cast<float2*>(&C[(long)(row0    ) * N + col0]) = make_float2(v00, v01);
            *reinterpret_cast<float2*>(&C[(long)(row0 + 8) * N + col0]) = make_float2(v10, v11);
        }
    }
}

// ---------------- route: logits + softmax + top-2 + (last block) scan/fill --
__global__ void route_kernel(const float* __restrict__ H1,
                             const float* __restrict__ Wr2,
                             const float* __restrict__ br2,
                             int*   __restrict__ topk_idx,
                             float* __restrict__ topk_w,
                             int*   __restrict__ counts,
                             int*   __restrict__ done,
                             int*   __restrict__ perm,
                             int*   __restrict__ slot,
                             int*   __restrict__ tile_expert)
{
    int warp = threadIdx.x >> 5, lane = threadIdx.x & 31;
    int t = blockIdx.x * 8 + warp;
    const float* h = H1 + (long)t * D_DIM;

    float acc[E_EXP];
    #pragma unroll
    for (int e = 0; e < E_EXP; e++) acc[e] = 0.0f;

    #pragma unroll 4
    for (int i = 0; i < D_DIM / 32; i++) {
        int d = i * 32 + lane;
        float hv = h[d];
        const float4* w4 = reinterpret_cast<const float4*>(Wr2 + (long)d * E_EXP);
        float4 wa = w4[0], wb = w4[1];
        acc[0] += hv * wa.x; acc[1] += hv * wa.y; acc[2] += hv * wa.z; acc[3] += hv * wa.w;
        acc[4] += hv * wb.x; acc[5] += hv * wb.y; acc[6] += hv * wb.z; acc[7] += hv * wb.w;
    }
    #pragma unroll
    for (int e = 0; e < E_EXP; e++)
        #pragma unroll
        for (int off = 16; off; off >>= 1)
            acc[e] += __shfl_xor_sync(0xFFFFFFFFu, acc[e], off);

    if (lane == 0) {
        float l[E_EXP];
        #pragma unroll
        for (int e = 0; e < E_EXP; e++) l[e] = acc[e] + br2[e];
        int e0 = 0;
        #pragma unroll
        for (int e = 1; e < E_EXP; e++) if (l[e] > l[e0]) e0 = e;
        int e1 = -1;
        #pragma unroll
        for (int e = 0; e < E_EXP; e++)
            if (e != e0 && (e1 < 0 || l[e] > l[e1])) e1 = e;
        float m  = l[e0];
        float p0 = expf(l[e0] - m);
        float p1 = expf(l[e1] - m);
        float inv = 1.0f / (p0 + p1);
        topk_idx[t * 2]     = e0;
        topk_idx[t * 2 + 1] = e1;
        topk_w[t * 2]       = p0 * inv;
        topk_w[t * 2 + 1]   = p1 * inv;
        atomicAdd(&counts[e0], 1);
        atomicAdd(&counts[e1], 1);
    }

    // ---- last-block: padded prefix scan + permutation fill ----
    __syncthreads();
    __shared__ int is_last;
    if (threadIdx.x == 0) {
        __threadfence();
        int prev = atomicAdd(done, 1);
        is_last = (prev == (int)gridDim.x - 1);
    }
    __syncthreads();
    if (!is_last) return;
    __threadfence();

    __shared__ int s_off[E_EXP + 1];
    __shared__ int s_fill[E_EXP];
    if (threadIdx.x == 0) {
        int off = 0;
        for (int e = 0; e < E_EXP; e++) {
            s_off[e] = off;
            off += (counts[e] + 127) & ~127;
        }
        s_off[E_EXP] = off;
        int e = 0;
        for (int tile = 0; tile < MTILES; tile++) {
            int r = tile * 128;
            if (r >= off) { tile_expert[tile] = -1; continue; }
            while (e < E_EXP && r >= s_off[e + 1]) e++;
            tile_expert[tile] = e;
        }
    }
    if (threadIdx.x < E_EXP) s_fill[threadIdx.x] = 0;
    __syncthreads();

    for (int tt = threadIdx.x; tt < T_TOK; tt += 256) {
        #pragma unroll
        for (int k = 0; k < 2; k++) {
            int e   = topk_idx[tt * 2 + k];
            int pos = s_off[e] + atomicAdd(&s_fill[e], 1);
            perm[pos]        = tt;
            slot[tt * 2 + k] = pos;
        }
    }
}

// ---------------- combine ----------------
__global__ void combine_kernel(const float* __restrict__ y,
                               const int*   __restrict__ slot,
                               const float* __restrict__ w,
                               float* __restrict__ out)
{
    long i = (long)blockIdx.x * 256 + threadIdx.x;
    int  t = (int)(i >> 8);
    int  c = ((int)i & 255) * 4;
    int   s0 = slot[t * 2], s1 = slot[t * 2 + 1];
    float w0 = w[t * 2],    w1 = w[t * 2 + 1];
    float4 y0 = *reinterpret_cast<const float4*>(y + (long)s0 * D_DIM + c);
    float4 y1 = *reinterpret_cast<const float4*>(y + (long)s1 * D_DIM + c);
    float4 o;
    o.x = w0 * y0.x + w1 * y1.x;
    o.y = w0 * y0.y + w1 * y1.y;
    o.z = w0 * y0.z + w1 * y1.z;
    o.w = w0 * y0.w + w1 * y1.w;
    *reinterpret_cast<float4*>(out + (long)t * D_DIM + c) = o;
}

// ---------------- launch ----------------
extern "C" void kernel_launch(void* const* d_in, const int* in_sizes, int n_in,
                              void* d_out, int out_size)
{
    const float* x   = (const float*)d_in[0];
    const float* Wr1 = (const float*)d_in[1];
    const float* br1 = (const float*)d_in[2];
    const float* Wr2 = (const float*)d_in[3];
    const float* br2 = (const float*)d_in[4];
    const float* W1  = (const float*)d_in[5];
    const float* b1  = (const float*)d_in[6];
    const float* W2  = (const float*)d_in[7];
    const float* b2  = (const float*)d_in[8];
    float* out = (float*)d_out;

    void *pH1, *ph, *py, *pW1c, *pW2c, *pxhi, *pxlo, *pwh, *pwl;
    void *pti, *ptw, *pc, *pp, *ps, *pte, *pd;
    cudaGetSymbolAddress(&pH1,  g_H1);
    cudaGetSymbolAddress(&ph,   g_h);
    cudaGetSymbolAddress(&py,   g_y);
    cudaGetSymbolAddress(&pW1c, g_W1c);
    cudaGetSymbolAddress(&pW2c, g_W2c);
    cudaGetSymbolAddress(&pxhi, g_xhi);
    cudaGetSymbolAddress(&pxlo, g_xlo);
    cudaGetSymbolAddress(&pwh,  g_wr1hi);
    cudaGetSymbolAddress(&pwl,  g_wr1lo);
    cudaGetSymbolAddress(&pti,  g_topk_idx);
    cudaGetSymbolAddress(&ptw,  g_topk_w);
    cudaGetSymbolAddress(&pc,   g_counts);
    cudaGetSymbolAddress(&pp,   g_perm);
    cudaGetSymbolAddress(&ps,   g_slot);
    cudaGetSymbolAddress(&pte,  g_tile_expert);
    cudaGetSymbolAddress(&pd,   g_done);

    cudaFuncSetAttribute(gemm_split3_kernel,
                         cudaFuncAttributeMaxDynamicSharedMemorySize, SPLIT_SMEM_BYTES);
    cudaFuncSetAttribute(gemm_tf32_kernel<true,  true,  true,  true>,
                         cudaFuncAttributeMaxDynamicSharedMemorySize, GEMM_SMEM_BYTES);
    cudaFuncSetAttribute(gemm_tf32_kernel<false, false, false, true>,
                         cudaFuncAttributeMaxDynamicSharedMemorySize, GEMM_SMEM_BYTES);

    // 0) prep: init perm/counts/done, round W1/W2 to tf32, split x and Wr1
    long nprep4 = (W1E + W2E + XE + WR1E) / 4;
    prep_kernel<<<(unsigned)((nprep4 + 255) / 256), 256>>>(
        (const float4*)W1, (const float4*)W2, (const float4*)x, (const float4*)Wr1,
        (float4*)pW1c, (float4*)pW2c, (float4*)pxhi, (float4*)pxlo,
        (float4*)pwh, (float4*)pwl,
        (int*)pp, (int*)pc, (int*)pd);

    // 1) router hidden: H1 = GELU(x @ Wr1 + br1), 3xTF32 split from pre-split operands
    gemm_split3_kernel<<<dim3(D_DIM / BN, T_TOK / BM), 256, SPLIT_SMEM_BYTES>>>(
        (const float*)pxhi, (const float*)pxlo, (const float*)pwh, (const float*)pwl,
        br1, (float*)pH1, D_DIM, D_DIM);

    // 2) logits + softmax + top-2 + counts + (last block) scan + fill
    route_kernel<<<T_TOK / 8, 256>>>((const float*)pH1, Wr2, br2,
                                     (int*)pti, (float*)ptw, (int*)pc, (int*)pd,
                                     (int*)pp, (int*)ps, (int*)pte);

    // 3) expert layer 1 (grouped, gathered): h = rna(GELU(xhi[perm] @ W1c + b1))
    gemm_tf32_kernel<true, true, true, true>
        <<<dim3(H_DIM / BN, MTILES), 256, GEMM_SMEM_BYTES>>>(
            (const float*)pxhi, (const float*)pW1c, b1, (float*)ph, H_DIM, D_DIM,
            (const int*)pp, (const int*)pte, (long)D_DIM * H_DIM, H_DIM);

    // 4) expert layer 2 (grouped): y = h @ W2c + b2
    gemm_tf32_kernel<false, false, false, true>
        <<<dim3(D_DIM / BN, MTILES), 256, GEMM_SMEM_BYTES>>>(
            (const float*)ph, (const float*)pW2c, b2, (float*)py, D_DIM, H_DIM,
            nullptr, (const int*)pte, (long)H_DIM * D_DIM, D_DIM);

    // 5) weighted combine via recorded slots
    combine_kernel<<<(T_TOK * D_DIM / 4) / 256, 256>>>(
        (const float*)py, (const int*)ps, (const float*)ptw, out);
}

// round 3
// speedup vs baseline: 1.8893x; 1.8826x over previous
#include <cuda_runtime.h>
#include <cuda_fp16.h>
#include <cstdint>
#include <cmath>

// ---------------- problem constants ----------------
#define T_TOK  8192          // B*S tokens
#define D_DIM  1024
#define E_EXP  8
#define H_DIM  4096
#define MPAD   17408         // T*K + E*128 padding headroom (multiple of 128)
#define MTILES 136           // MPAD / 128

#define W1E  33554432L       // 8*1024*4096
#define W2E  33554432L
#define XE   8388608L        // 8192*1024
#define WR1E 1048576L        // 1024*1024

// ---------------- scratch (device globals; no allocation allowed) ----------
__device__ float  g_H1[(size_t)T_TOK * D_DIM];   // router hidden (fp32)
__device__ __half g_h [(size_t)MPAD * H_DIM];    // expert hidden (fp16)
__device__ float  g_y [(size_t)MPAD * D_DIM];    // expert out (fp32)
__device__ __half g_W1h[W1E];                    // fp16(W1)
__device__ __half g_W2h[W2E];                    // fp16(W2)
__device__ __half g_xh[XE];                      // fp16(x)
__device__ __half g_xl[XE];                      // fp16(x - xh)
__device__ __half g_wh[WR1E];                    // fp16(Wr1)
__device__ __half g_wl[WR1E];                    // fp16(Wr1 - wh)
__device__ int    g_topk_idx[T_TOK * 2];
__device__ float  g_topk_w [T_TOK * 2];
__device__ int    g_counts [E_EXP];
__device__ int    g_perm   [MPAD];
__device__ int    g_slot   [T_TOK * 2];
__device__ int    g_tile_expert[MTILES];
__device__ int    g_done;

// ---------------- helpers ----------------
__device__ __forceinline__ float gelu_exact(float x) {
    return 0.5f * x * (1.0f + erff(x * 0.70710678118654752440f));
}
__device__ __forceinline__ void mma_f16(float c[4],
                                        uint32_t a0, uint32_t a1, uint32_t a2, uint32_t a3,
                                        uint32_t b0, uint32_t b1) {
    asm volatile(
        "mma.sync.aligned.m16n8k16.row.col.f32.f16.f16.f32 "
        "{%0,%1,%2,%3}, {%4,%5,%6,%7}, {%8,%9}, {%0,%1,%2,%3};\n"
        : "+f"(c[0]), "+f"(c[1]), "+f"(c[2]), "+f"(c[3])
        : "r"(a0), "r"(a1), "r"(a2), "r"(a3), "r"(b0), "r"(b1));
}
__device__ __forceinline__ void ldsm_x4(uint32_t& r0, uint32_t& r1, uint32_t& r2, uint32_t& r3,
                                        uint32_t addr) {
    asm volatile("ldmatrix.sync.aligned.m8n8.x4.shared.b16 {%0,%1,%2,%3}, [%4];"
                 : "=r"(r0), "=r"(r1), "=r"(r2), "=r"(r3) : "r"(addr));
}
__device__ __forceinline__ void ldsm_x4_t(uint32_t& r0, uint32_t& r1, uint32_t& r2, uint32_t& r3,
                                          uint32_t addr) {
    asm volatile("ldmatrix.sync.aligned.m8n8.x4.trans.shared.b16 {%0,%1,%2,%3}, [%4];"
                 : "=r"(r0), "=r"(r1), "=r"(r2), "=r"(r3) : "r"(addr));
}
__device__ __forceinline__ void cp_async16(void* smem_dst, const void* gmem_src, unsigned src_bytes) {
    unsigned d = (unsigned)__cvta_generic_to_shared(smem_dst);
    asm volatile("cp.async.ca.shared.global [%0], [%1], 16, %2;\n"
                 :: "r"(d), "l"(gmem_src), "r"(src_bytes) : "memory");
}

// ---------------- GEMM tiling constants (fp16) ----------------
constexpr int BM = 128, BN = 128, BK = 32;       // BK in halves
constexpr int AS = 40;                           // A smem stride (halves) -> LDSM conflict-free
constexpr int BS = 136;                          // B smem stride (halves) -> LDSM conflict-free
constexpr int A_HELE = BM * AS;                  // 5120 halves / stage
constexpr int B_HELE = BK * BS;                  // 4352 halves / stage
constexpr int GEMM_SMEM_BYTES  = (2 * A_HELE + 2 * B_HELE) * 2;            // 37888
constexpr int SPLIT_SMEM_BYTES = (4 * A_HELE + 4 * B_HELE) * 2;            // 75776

// ---------------- prep: init + fp16 conversions ----------------
__global__ void prep_kernel(const float4* __restrict__ W1, const float4* __restrict__ W2,
                            const float4* __restrict__ x,  const float4* __restrict__ Wr1,
                            __half* __restrict__ W1h, __half* __restrict__ W2h,
                            __half* __restrict__ xh,  __half* __restrict__ xl,
                            __half* __restrict__ wh,  __half* __restrict__ wl,
                            int* __restrict__ perm, int* __restrict__ counts,
                            int* __restrict__ done)
{
    long i = (long)blockIdx.x * 256 + threadIdx.x;
    if (i < MPAD)  perm[i] = -1;
    if (i < E_EXP) counts[i] = 0;
    if (i == 0)    *done = 0;

    if (i < W1E / 4) {
        float4 v = W1[i];
        __half2* p = reinterpret_cast<__half2*>(W1h + i * 4);
        p[0] = __floats2half2_rn(v.x, v.y);
        p[1] = __floats2half2_rn(v.z, v.w);
    } else if (i < (W1E + W2E) / 4) {
        long j = i - W1E / 4;
        float4 v = W2[j];
        __half2* p = reinterpret_cast<__half2*>(W2h + j * 4);
        p[0] = __floats2half2_rn(v.x, v.y);
        p[1] = __floats2half2_rn(v.z, v.w);
    } else if (i < (W1E + W2E + XE) / 4) {
        long j = i - (W1E + W2E) / 4;
        float4 v = x[j];
        __half h0 = __float2half_rn(v.x), h1 = __float2half_rn(v.y);
        __half h2 = __float2half_rn(v.z), h3 = __float2half_rn(v.w);
        __half2* ph = reinterpret_cast<__half2*>(xh + j * 4);
        ph[0] = __halves2half2(h0, h1);
        ph[1] = __halves2half2(h2, h3);
        __half2* pl = reinterpret_cast<__half2*>(xl + j * 4);
        pl[0] = __floats2half2_rn(v.x - __half2float(h0), v.y - __half2float(h1));
        pl[1] = __floats2half2_rn(v.z - __half2float(h2), v.w - __half2float(h3));
    } else if (i < (W1E + W2E + XE + WR1E) / 4) {
        long j = i - (W1E + W2E + XE) / 4;
        float4 v = Wr1[j];
        __half h0 = __float2half_rn(v.x), h1 = __float2half_rn(v.y);
        __half h2 = __float2half_rn(v.z), h3 = __float2half_rn(v.w);
        __half2* ph = reinterpret_cast<__half2*>(wh + j * 4);
        ph[0] = __halves2half2(h0, h1);
        ph[1] = __halves2half2(h2, h3);
        __half2* pl = reinterpret_cast<__half2*>(wl + j * 4);
        pl[0] = __floats2half2_rn(v.x - __half2float(h0), v.y - __half2float(h1));
        pl[1] = __floats2half2_rn(v.z - __half2float(h2), v.w - __half2float(h3));
    }
}

// ---------------- fp16 GEMM (ldmatrix + m16n8k16) ----------------
// C[M,N] = act( A[M,K] @ B[K,N] + bias[N] )
template<bool DO_GELU, bool OUT_HALF, bool GATHER, bool EXPERT>
__global__ __launch_bounds__(256, 2)
void gemm_f16_kernel(const __half* __restrict__ A,
                     const __half* __restrict__ Bbase,
                     const float* __restrict__ biasBase,
                     void* __restrict__ Cv,
                     int N, int Kdim,
                     const int* __restrict__ perm,
                     const int* __restrict__ tile_expert,
                     long strideB, int strideBias)
{
    extern __shared__ __half smem[];
    __half* As = smem;                          // [2][A_HELE]
    __half* Bs = smem + 2 * A_HELE;             // [2][B_HELE]

    const int mtile = blockIdx.y;
    const int ntile = blockIdx.x;

    const __half* Bp  = Bbase;
    const float* bias = biasBase;
    if (EXPERT) {
        int e = tile_expert[mtile];
        if (e < 0) return;
        Bp   += (long)e * strideB;
        bias += (long)e * strideBias;
    }

    const int tid   = threadIdx.x;
    const int lane  = tid & 31;
    const int warp  = tid >> 5;
    const int warpM = warp & 1;                 // 0..1 (64 rows each)
    const int warpN = warp >> 1;                // 0..3 (32 cols each)
    const int mbase = mtile * BM;
    const int nbase = ntile * BN;

    float acc[4][4][4];
    #pragma unroll
    for (int mi = 0; mi < 4; mi++)
        #pragma unroll
        for (int ni = 0; ni < 4; ni++)
            #pragma unroll
            for (int r = 0; r < 4; r++) acc[mi][ni][r] = 0.0f;

    const int KT = Kdim / BK;

    auto load_tiles = [&](int kt, int stage) {
        const int k0 = kt * BK;
        // A: 128 rows x 32 halves (64B = 4 chunks) -> 512 chunks, 2/thread
        #pragma unroll
        for (int i = 0; i < 2; i++) {
            int c   = tid + i * 256;
            int r   = c >> 2;
            int off = (c & 3) * 8;              // halves
            const __half* src;
            unsigned sz = 16;
            if (GATHER) {
                int g = perm[mbase + r];
                if (g < 0) { sz = 0; src = A; }
                else        src = A + (long)g * Kdim + k0 + off;
            } else {
                src = A + (long)(mbase + r) * Kdim + k0 + off;
            }
            cp_async16(&As[stage * A_HELE + r * AS + off], src, sz);
        }
        // B: 32 rows x 128 halves (256B = 16 chunks) -> 512 chunks, 2/thread
        #pragma unroll
        for (int i = 0; i < 2; i++) {
            int c   = tid + i * 256;
            int r   = c >> 4;
            int off = (c & 15) * 8;
            const __half* src = Bp + (long)(k0 + r) * N + nbase + off;
            cp_async16(&Bs[stage * B_HELE + r * BS + off], src, 16);
        }
        asm volatile("cp.async.commit_group;\n" ::: "memory");
    };

    const uint32_t as_u = (uint32_t)__cvta_generic_to_shared(As);
    const uint32_t bs_u = (uint32_t)__cvta_generic_to_shared(Bs);
    const int tl = lane >> 3;                   // tile index within LDSM.x4
    const int lr = lane & 7;                    // row within 8x8 tile
    // A address components (halves): row = warpM*64 + mi*16 + (tl&1)*8 + lr ; col = ks*16 + (tl>>1)*8
    const int a_row0 = warpM * 64 + (tl & 1) * 8 + lr;
    const int a_col0 = (tl >> 1) * 8;
    // B (trans) : krow = ks*16 + (tl&1)*8 + lr ; col = warpN*32 + nj*16 + (tl>>1)*8
    const int b_krow0 = (tl & 1) * 8 + lr;
    const int b_col0  = warpN * 32 + (tl >> 1) * 8;

    load_tiles(0, 0);
    for (int kt = 0; kt < KT; kt++) {
        if (kt + 1 < KT) {
            load_tiles(kt + 1, (kt + 1) & 1);
            asm volatile("cp.async.wait_group 1;\n" ::: "memory");
        } else {
            asm volatile("cp.async.wait_group 0;\n" ::: "memory");
        }
        __syncthreads();

        const uint32_t asu = as_u + (kt & 1) * (A_HELE * 2);
        const uint32_t bsu = bs_u + (kt & 1) * (B_HELE * 2);

        #pragma unroll
        for (int ks = 0; ks < 2; ks++) {
            uint32_t a[4][4];
            #pragma unroll
            for (int mi = 0; mi < 4; mi++)
                ldsm_x4(a[mi][0], a[mi][1], a[mi][2], a[mi][3],
                        asu + ((a_row0 + mi * 16) * AS + ks * 16 + a_col0) * 2);
            uint32_t b[4][2];
            #pragma unroll
            for (int nj = 0; nj < 2; nj++)
                ldsm_x4_t(b[2 * nj][0], b[2 * nj][1], b[2 * nj + 1][0], b[2 * nj + 1][1],
                          bsu + ((b_krow0 + ks * 16) * BS + b_col0 + nj * 16) * 2);
            #pragma unroll
            for (int mi = 0; mi < 4; mi++)
                #pragma unroll
                for (int ni = 0; ni < 4; ni++)
                    mma_f16(acc[mi][ni], a[mi][0], a[mi][1], a[mi][2], a[mi][3],
                            b[ni][0], b[ni][1]);
        }
        __syncthreads();
    }

    // epilogue
    #pragma unroll
    for (int mi = 0; mi < 4; mi++) {
        #pragma unroll
        for (int ni = 0; ni < 4; ni++) {
            int row0 = mbase + warpM * 64 + mi * 16 + (lane >> 2);
            int col0 = nbase + warpN * 32 + ni * 8 + (lane & 3) * 2;
            float bv0 = bias[col0], bv1 = bias[col0 + 1];
            float v00 = acc[mi][ni][0] + bv0;
            float v01 = acc[mi][ni][1] + bv1;
            float v10 = acc[mi][ni][2] + bv0;
            float v11 = acc[mi][ni][3] + bv1;
            if (DO_GELU) {
                v00 = gelu_exact(v00); v01 = gelu_exact(v01);
                v10 = gelu_exact(v10); v11 = gelu_exact(v11);
            }
            if (OUT_HALF) {
                __half* C = (__half*)Cv;
                *reinterpret_cast<__half2*>(C + (long)(row0    ) * N + col0) = __floats2half2_rn(v00, v01);
                *reinterpret_cast<__half2*>(C + (long)(row0 + 8) * N + col0) = __floats2half2_rn(v10, v11);
            } else {
                float* C = (float*)Cv;
                *reinterpret_cast<float2*>(C + (long)(row0    ) * N + col0) = make_float2(v00, v01);
                *reinterpret_cast<float2*>(C + (long)(row0 + 8) * N + col0) = make_float2(v10, v11);
            }
        }
    }
}

// ---------------- router GEMM: fp16 hi/lo split, 3 mma terms ----------------
// C = GELU( (Ah+Al) @ (Bh+Bl) + bias ), dropping Al*Bl (~2^-22).
__global__ __launch_bounds__(256, 2)
void gemm_split_f16_kernel(const __half* __restrict__ Ahi, const __half* __restrict__ Alo,
                           const __half* __restrict__ Bhi, const __half* __restrict__ Blo,
                           const float* __restrict__ bias,
                           float* __restrict__ C, int N, int Kdim)
{
    extern __shared__ __half smem[];
    __half* AsH = smem;                         // [2][A_HELE]
    __half* AsL = AsH + 2 * A_HELE;
    __half* BsH = AsL + 2 * A_HELE;             // [2][B_HELE]
    __half* BsL = BsH + 2 * B_HELE;

    const int mtile = blockIdx.y;
    const int ntile = blockIdx.x;
    const int tid   = threadIdx.x;
    const int lane  = tid & 31;
    const int warp  = tid >> 5;
    const int warpM = warp & 1;
    const int warpN = warp >> 1;
    const int mbase = mtile * BM;
    const int nbase = ntile * BN;

    float acc[4][4][4];
    #pragma unroll
    for (int mi = 0; mi < 4; mi++)
        #pragma unroll
        for (int ni = 0; ni < 4; ni++)
            #pragma unroll
            for (int r = 0; r < 4; r++) acc[mi][ni][r] = 0.0f;

    const int KT = Kdim / BK;

    auto load_tiles = [&](int kt, int stage) {
        const int k0 = kt * BK;
        #pragma unroll
        for (int i = 0; i < 2; i++) {
            int c   = tid + i * 256;
            int r   = c >> 2;
            int off = (c & 3) * 8;
            long go = (long)(mbase + r) * Kdim + k0 + off;
            cp_async16(&AsH[stage * A_HELE + r * AS + off], Ahi + go, 16);
            cp_async16(&AsL[stage * A_HELE + r * AS + off], Alo + go, 16);
        }
        #pragma unroll
        for (int i = 0; i < 2; i++) {
            int c   = tid + i * 256;
            int r   = c >> 4;
            int off = (c & 15) * 8;
            long go = (long)(k0 + r) * N + nbase + off;
            cp_async16(&BsH[stage * B_HELE + r * BS + off], Bhi + go, 16);
            cp_async16(&BsL[stage * B_HELE + r * BS + off], Blo + go, 16);
        }
        asm volatile("cp.async.commit_group;\n" ::: "memory");
    };

    const uint32_t ash_u = (uint32_t)__cvta_generic_to_shared(AsH);
    const uint32_t asl_u = (uint32_t)__cvta_generic_to_shared(AsL);
    const uint32_t bsh_u = (uint32_t)__cvta_generic_to_shared(BsH);
    const uint32_t bsl_u = (uint32_t)__cvta_generic_to_shared(BsL);
    const int tl = lane >> 3;
    const int lr = lane & 7;
    const int a_row0 = warpM * 64 + (tl & 1) * 8 + lr;
    const int a_col0 = (tl >> 1) * 8;
    const int b_krow0 = (tl & 1) * 8 + lr;
    const int b_col0  = warpN * 32 + (tl >> 1) * 8;

    load_tiles(0, 0);
    for (int kt = 0; kt < KT; kt++) {
        if (kt + 1 < KT) {
            load_tiles(kt + 1, (kt + 1) & 1);
            asm volatile("cp.async.wait_group 1;\n" ::: "memory");
        } else {
            asm volatile("cp.async.wait_group 0;\n" ::: "memory");
        }
        __syncthreads();

        const uint32_t ashu = ash_u + (kt & 1) * (A_HELE * 2);
        const uint32_t aslu = asl_u + (kt & 1) * (A_HELE * 2);
        const uint32_t bshu = bsh_u + (kt & 1) * (B_HELE * 2);
        const uint32_t bslu = bsl_u + (kt & 1) * (B_HELE * 2);

        #pragma unroll
        for (int ks = 0; ks < 2; ks++) {
            uint32_t ah[4][4], al[4][4];
            #pragma unroll
            for (int mi = 0; mi < 4; mi++) {
                uint32_t off = ((a_row0 + mi * 16) * AS + ks * 16 + a_col0) * 2;
                ldsm_x4(ah[mi][0], ah[mi][1], ah[mi][2], ah[mi][3], ashu + off);
                ldsm_x4(al[mi][0], al[mi][1], al[mi][2], al[mi][3], aslu + off);
            }
            uint32_t bh[4][2], bl[4][2];
            #pragma unroll
            for (int nj = 0; nj < 2; nj++) {
                uint32_t off = ((b_krow0 + ks * 16) * BS + b_col0 + nj * 16) * 2;
                ldsm_x4_t(bh[2 * nj][0], bh[2 * nj][1], bh[2 * nj + 1][0], bh[2 * nj + 1][1], bshu + off);
                ldsm_x4_t(bl[2 * nj][0], bl[2 * nj][1], bl[2 * nj + 1][0], bl[2 * nj + 1][1], bslu + off);
            }
            #pragma unroll
            for (int mi = 0; mi < 4; mi++)
                #pragma unroll
                for (int ni = 0; ni < 4; ni++) {
                    mma_f16(acc[mi][ni], ah[mi][0], ah[mi][1], ah[mi][2], ah[mi][3],
                            bl[ni][0], bl[ni][1]);
                    mma_f16(acc[mi][ni], al[mi][0], al[mi][1], al[mi][2], al[mi][3],
                            bh[ni][0], bh[ni][1]);
                    mma_f16(acc[mi][ni], ah[mi][0], ah[mi][1], ah[mi][2], ah[mi][3],
                            bh[ni][0], bh[ni][1]);
                }
        }
        __syncthreads();
    }

    #pragma unroll
    for (int mi = 0; mi < 4; mi++) {
        #pragma unroll
        for (int ni = 0; ni < 4; ni++) {
            int row0 = mbase + warpM * 64 + mi * 16 + (lane >> 2);
            int col0 = nbase + warpN * 32 + ni * 8 + (lane & 3) * 2;
            float bv0 = bias[col0], bv1 = bias[col0 + 1];
            float v00 = gelu_exact(acc[mi][ni][0] + bv0);
            float v01 = gelu_exact(acc[mi][ni][1] + bv1);
            float v10 = gelu_exact(acc[mi][ni][2] + bv0);
            float v11 = gelu_exact(acc[mi][ni][3] + bv1);
            *reinterpret_cast<float2*>(&C[(long)(row0    ) * N + col0]) = make_float2(v00, v01);
            *reinterpret_cast<float2*>(&C[(long)(row0 + 8) * N + col0]) = make_float2(v10, v11);
        }
    }
}

// ---------------- route: logits + softmax + top-2 + (last block) scan/fill --
__global__ void route_kernel(const float* __restrict__ H1,
                             const float* __restrict__ Wr2,
                             const float* __restrict__ br2,
                             int*   __restrict__ topk_idx,
                             float* __restrict__ topk_w,
                             int*   __restrict__ counts,
                             int*   __restrict__ done,
                             int*   __restrict__ perm,
                             int*   __restrict__ slot,
                             int*   __restrict__ tile_expert)
{
    int warp = threadIdx.x >> 5, lane = threadIdx.x & 31;
    int t = blockIdx.x * 8 + warp;
    const float* h = H1 + (long)t * D_DIM;

    float acc[E_EXP];
    #pragma unroll
    for (int e = 0; e < E_EXP; e++) acc[e] = 0.0f;

    #pragma unroll 4
    for (int i = 0; i < D_DIM / 32; i++) {
        int d = i * 32 + lane;
        float hv = h[d];
        const float4* w4 = reinterpret_cast<const float4*>(Wr2 + (long)d * E_EXP);
        float4 wa = w4[0], wb = w4[1];
        acc[0] += hv * wa.x; acc[1] += hv * wa.y; acc[2] += hv * wa.z; acc[3] += hv * wa.w;
        acc[4] += hv * wb.x; acc[5] += hv * wb.y; acc[6] += hv * wb.z; acc[7] += hv * wb.w;
    }
    #pragma unroll
    for (int e = 0; e < E_EXP; e++)
        #pragma unroll
        for (int off = 16; off; off >>= 1)
            acc[e] += __shfl_xor_sync(0xFFFFFFFFu, acc[e], off);

    if (lane == 0) {
        float l[E_EXP];
        #pragma unroll
        for (int e = 0; e < E_EXP; e++) l[e] = acc[e] + br2[e];
        int e0 = 0;
        #pragma unroll
        for (int e = 1; e < E_EXP; e++) if (l[e] > l[e0]) e0 = e;
        int e1 = -1;
        #pragma unroll
        for (int e = 0; e < E_EXP; e++)
            if (e != e0 && (e1 < 0 || l[e] > l[e1])) e1 = e;
        float m  = l[e0];
        float p0 = expf(l[e0] - m);
        float p1 = expf(l[e1] - m);
        float inv = 1.0f / (p0 + p1);
        topk_idx[t * 2]     = e0;
        topk_idx[t * 2 + 1] = e1;
        topk_w[t * 2]       = p0 * inv;
        topk_w[t * 2 + 1]   = p1 * inv;
        atomicAdd(&counts[e0], 1);
        atomicAdd(&counts[e1], 1);
    }

    // last-block: padded prefix scan + permutation fill
    __syncthreads();
    __shared__ int is_last;
    if (threadIdx.x == 0) {
        __threadfence();
        int prev = atomicAdd(done, 1);
        is_last = (prev == (int)gridDim.x - 1);
    }
    __syncthreads();
    if (!is_last) return;
    __threadfence();

    __shared__ int s_off[E_EXP + 1];
    __shared__ int s_fill[E_EXP];
    if (threadIdx.x == 0) {
        int off = 0;
        for (int e = 0; e < E_EXP; e++) {
            s_off[e] = off;
            off += (counts[e] + 127) & ~127;
        }
        s_off[E_EXP] = off;
        int e = 0;
        for (int tile = 0; tile < MTILES; tile++) {
            int r = tile * 128;
            if (r >= off) { tile_expert[tile] = -1; continue; }
            while (e < E_EXP && r >= s_off[e + 1]) e++;
            tile_expert[tile] = e;
        }
    }
    if (threadIdx.x < E_EXP) s_fill[threadIdx.x] = 0;
    __syncthreads();

    for (int tt = threadIdx.x; tt < T_TOK; tt += 256) {
        #pragma unroll
        for (int k = 0; k < 2; k++) {
            int e   = topk_idx[tt * 2 + k];
            int pos = s_off[e] + atomicAdd(&s_fill[e], 1);
            perm[pos]        = tt;
            slot[tt * 2 + k] = pos;
        }
    }
}

// ---------------- combine ----------------
__global__ void combine_kernel(const float* __restrict__ y,
                               const int*   __restrict__ slot,
                               const float* __restrict__ w,
                               float* __restrict__ out)
{
    long i = (long)blockIdx.x * 256 + threadIdx.x;
    int  t = (int)(i >> 8);
    int  c = ((int)i & 255) * 4;
    int   s0 = slot[t * 2], s1 = slot[t * 2 + 1];
    float w0 = w[t * 2],    w1 = w[t * 2 + 1];
    float4 y0 = *reinterpret_cast<const float4*>(y + (long)s0 * D_DIM + c);
    float4 y1 = *reinterpret_cast<const float4*>(y + (long)s1 * D_DIM + c);
    float4 o;
    o.x = w0 * y0.x + w1 * y1.x;
    o.y = w0 * y0.y + w1 * y1.y;
    o.z = w0 * y0.z + w1 * y1.z;
    o.w = w0 * y0.w + w1 * y1.w;
    *reinterpret_cast<float4*>(out + (long)t * D_DIM + c) = o;
}

// ---------------- launch ----------------
extern "C" void kernel_launch(void* const* d_in, const int* in_sizes, int n_in,
                              void* d_out, int out_size)
{
    const float* x   = (const float*)d_in[0];
    const float* Wr1 = (const float*)d_in[1];
    const float* br1 = (const float*)d_in[2];
    const float* Wr2 = (const float*)d_in[3];
    const float* br2 = (const float*)d_in[4];
    const float* W1  = (const float*)d_in[5];
    const float* b1  = (const float*)d_in[6];
    const float* W2  = (const float*)d_in[7];
    const float* b2  = (const float*)d_in[8];
    float* out = (float*)d_out;

    void *pH1, *ph, *py, *pW1h, *pW2h, *pxh, *pxl, *pwh, *pwl;
    void *pti, *ptw, *pc, *pp, *ps, *pte, *pd;
    cudaGetSymbolAddress(&pH1,  g_H1);
    cudaGetSymbolAddress(&ph,   g_h);
    cudaGetSymbolAddress(&py,   g_y);
    cudaGetSymbolAddress(&pW1h, g_W1h);
    cudaGetSymbolAddress(&pW2h, g_W2h);
    cudaGetSymbolAddress(&pxh,  g_xh);
    cudaGetSymbolAddress(&pxl,  g_xl);
    cudaGetSymbolAddress(&pwh,  g_wh);
    cudaGetSymbolAddress(&pwl,  g_wl);
    cudaGetSymbolAddress(&pti,  g_topk_idx);
    cudaGetSymbolAddress(&ptw,  g_topk_w);
    cudaGetSymbolAddress(&pc,   g_counts);
    cudaGetSymbolAddress(&pp,   g_perm);
    cudaGetSymbolAddress(&ps,   g_slot);
    cudaGetSymbolAddress(&pte,  g_tile_expert);
    cudaGetSymbolAddress(&pd,   g_done);

    cudaFuncSetAttribute(gemm_split_f16_kernel,
                         cudaFuncAttributeMaxDynamicSharedMemorySize, SPLIT_SMEM_BYTES);

    // 0) prep: init + fp16 conversions
    long nprep4 = (W1E + W2E + XE + WR1E) / 4;
    prep_kernel<<<(unsigned)((nprep4 + 255) / 256), 256>>>(
        (const float4*)W1, (const float4*)W2, (const float4*)x, (const float4*)Wr1,
        (__half*)pW1h, (__half*)pW2h, (__half*)pxh, (__half*)pxl,
        (__half*)pwh, (__half*)pwl,
        (int*)pp, (int*)pc, (int*)pd);

    // 1) router hidden: H1 = GELU(x @ Wr1 + br1), fp16 split (near-fp32)
    gemm_split_f16_kernel<<<dim3(D_DIM / BN, T_TOK / BM), 256, SPLIT_SMEM_BYTES>>>(
        (const __half*)pxh, (const __half*)pxl, (const __half*)pwh, (const __half*)pwl,
        br1, (float*)pH1, D_DIM, D_DIM);

    // 2) logits + softmax + top-2 + counts + (last block) scan + fill
    route_kernel<<<T_TOK / 8, 256>>>((const float*)pH1, Wr2, br2,
                                     (int*)pti, (float*)ptw, (int*)pc, (int*)pd,
                                     (int*)pp, (int*)ps, (int*)pte);

    // 3) expert layer 1 (grouped, gathered): h = fp16(GELU(xh[perm] @ W1h + b1))
    gemm_f16_kernel<true, true, true, true>
        <<<dim3(H_DIM / BN, MTILES), 256, GEMM_SMEM_BYTES>>>(
            (const __half*)pxh, (const __half*)pW1h, b1, ph, H_DIM, D_DIM,
            (const int*)pp, (const int*)pte, (long)D_DIM * H_DIM, H_DIM);

    // 4) expert layer 2 (grouped): y = h @ W2h + b2
    gemm_f16_kernel<false, false, false, true>
        <<<dim3(D_DIM / BN, MTILES), 256, GEMM_SMEM_BYTES>>>(
            (const __half*)ph, (const __half*)pW2h, b2, py, D_DIM, H_DIM,
            nullptr, (const int*)pte, (long)H_DIM * D_DIM, D_DIM);

    // 5) weighted combine via recorded slots
    combine_kernel<<<(T_TOK * D_DIM / 4) / 256, 256>>>(
        (const float*)py, (const int*)ps, (const float*)ptw, out);
}